// round 2
// baseline (speedup 1.0000x reference)
#include <cuda_runtime.h>
#include <math.h>

#define NROWS 8192      // B*T
#define HD    640       // hidden
#define NP    230       // phones
#define NM    96        // phonemes
#define BM    32        // rows per block
#define BK    32        // k tile
#define BN    256       // padded phone dim
#define P_PAD 233       // odd stride: conflict-free per-row phone reads
#define M_PAD 97
#define MAXPAIR 8

// smem layout (float offsets):
//  [0,1024)        sA[32][32]
//  [1024,9216)     sB[32][256]
//  [0,7456)        sPhone[32][233]   (aliases GEMM region after mainloop)
//  [9216,12320)    sPh[32][97]
//  [12320,12352)   sMax[32]
//  [12352,12384)   sLse[32]
//  [12384,12614)   sCnt[230] (int)
//  [12614,13074)   sIdx[1840 bytes]
#define SMEM_FLOATS 13074
#define SMEM_BYTES  (SMEM_FLOATS * 4)

__device__ int           g_cnt[NP];
__device__ unsigned char g_idx[NP * MAXPAIR];

// Compress the 0/1 (96 x 230) map into per-phone phoneme lists.
__global__ void build_pairs_kernel(const float* __restrict__ mapping) {
    int p = blockIdx.x * blockDim.x + threadIdx.x;
    if (p >= NP) return;
    int c = 0;
    for (int m = 0; m < NM; m++) {
        if (mapping[m * NP + p] > 0.0f) {
            if (c < MAXPAIR) g_idx[p * MAXPAIR + c] = (unsigned char)m;
            c++;
        }
    }
    g_cnt[p] = (c < MAXPAIR) ? c : MAXPAIR;
}

__global__ __launch_bounds__(256, 2)
void phon_kernel(const float* __restrict__ enc,
                 const float* __restrict__ f2p,
                 float* __restrict__ out) {
    extern __shared__ float sm[];
    float*         sA     = sm;                       // [32][32]
    float*         sB     = sm + 1024;                // [32][256]
    float*         sPhone = sm;                       // [32][233] aliases GEMM region
    float*         sPh    = sm + 9216;                // [32][97]
    float*         sMax   = sm + 12320;
    float*         sLse   = sm + 12352;
    int*           sCnt   = (int*)(sm + 12384);       // [230]
    unsigned char* sIdx   = (unsigned char*)(sm + 12614);

    const int tid  = threadIdx.x;
    const int tc   = tid & 63;   // column group 0..63
    const int tr   = tid >> 6;   // row group 0..3
    const int row0 = blockIdx.x * BM;

    // stage pair tables into smem (covered by first __syncthreads below)
    if (tid < NP) sCnt[tid] = g_cnt[tid];
    for (int i = tid; i < NP * MAXPAIR; i += 256) sIdx[i] = g_idx[i];

    float acc[8][4];
    #pragma unroll
    for (int i = 0; i < 8; i++)
        #pragma unroll
        for (int j = 0; j < 4; j++) acc[i][j] = 0.0f;

    for (int kt = 0; kt < HD; kt += BK) {
        // A tile: one float4 per thread, coalesced
        {
            int r  = tid >> 3;
            int k4 = (tid & 7) << 2;
            const float4 v = *reinterpret_cast<const float4*>(
                enc + (size_t)(row0 + r) * HD + kt + k4);
            float* d = sA + r * BK + k4;
            d[0] = v.x; d[1] = v.y; d[2] = v.z; d[3] = v.w;
        }
        // B tile: 32 iterations, zero-pad cols >= 230 (no guards in mainloop)
        #pragma unroll
        for (int it = 0; it < (BK * BN) / 256; it++) {
            int idx = tid + it * 256;
            int k = idx >> 8;
            int j = idx & 255;
            sB[idx] = (j < NP) ? f2p[(kt + k) * NP + j] : 0.0f;
        }
        __syncthreads();

        #pragma unroll 8
        for (int k = 0; k < BK; k++) {
            float a[8], b[4];
            #pragma unroll
            for (int i = 0; i < 8; i++) a[i] = sA[(tr * 8 + i) * BK + k];  // warp-broadcast
            #pragma unroll
            for (int j = 0; j < 4; j++) b[j] = sB[k * BN + tc + 64 * j];   // conflict-free
            #pragma unroll
            for (int i = 0; i < 8; i++)
                #pragma unroll
                for (int j = 0; j < 4; j++) acc[i][j] = fmaf(a[i], b[j], acc[i][j]);
        }
        __syncthreads();
    }

    // ---- epilogue ----
    const float scale = 0.039528470752104741f;  // 1/sqrt(640)

    // write phone logits into (aliased) smem
    #pragma unroll
    for (int i = 0; i < 8; i++) {
        int r = tr * 8 + i;
        #pragma unroll
        for (int j = 0; j < 4; j++) {
            int c = tc + 64 * j;
            if (c < NP) sPhone[r * P_PAD + c] = acc[i][j] * scale;
        }
    }
    // init phoneme buffer
    for (int idx = tid; idx < BM * NM; idx += 256)
        sPh[(idx / NM) * M_PAD + (idx % NM)] = -INFINITY;
    __syncthreads();

    // per-row scatter-max over compressed mapping, then max + logsumexp
    if (tid < BM) {
        const int r = tid;
        const float* phrow = sPhone + r * P_PAD;  // stride 233: conflict-free across lanes
        float*       phm   = sPh    + r * M_PAD;  // stride 97:  conflict-free across lanes
        for (int p = 0; p < NP; p++) {
            float v = phrow[p];
            int   c = sCnt[p];            // broadcast
            const unsigned char* ix = sIdx + p * MAXPAIR;
            for (int j = 0; j < c; j++) {
                int m = ix[j];
                if (v > phm[m]) phm[m] = v;
            }
        }
        float mx = -INFINITY;
        for (int m = 0; m < NM; m++) mx = fmaxf(mx, phm[m]);
        float s = 0.0f;
        for (int m = 0; m < NM; m++) s += expf(phm[m] - mx);
        sMax[r] = mx;
        sLse[r] = logf(s);
    }
    __syncthreads();

    // coalesced output writes
    for (int idx = tid; idx < BM * NM; idx += 256) {
        int r = idx / NM;
        int m = idx - r * NM;
        out[(size_t)(row0 + r) * NM + m] = sPh[r * M_PAD + m] - sMax[r] - sLse[r];
    }
}

extern "C" void kernel_launch(void* const* d_in, const int* in_sizes, int n_in,
                              void* d_out, int out_size) {
    const float* enc     = (const float*)d_in[0];
    const float* f2p     = (const float*)d_in[1];
    const float* mapping = (const float*)d_in[2];
    float*       out     = (float*)d_out;

    cudaFuncSetAttribute(phon_kernel,
                         cudaFuncAttributeMaxDynamicSharedMemorySize, SMEM_BYTES);

    build_pairs_kernel<<<1, 256>>>(mapping);
    phon_kernel<<<NROWS / BM, 256, SMEM_BYTES>>>(enc, f2p, out);
}

// round 5
// speedup vs baseline: 2.8155x; 2.8155x over previous
#include <cuda_runtime.h>
#include <math.h>
#include <stdint.h>

#define NROWS 8192      // B*T
#define HD    640
#define NP    230
#define NM    96
#define TM    64        // rows per CTA
#define TN    256       // padded phone dim
#define KC    32        // k per chunk
#define NCHUNK (HD / KC)  // 20
#define A_PAD 36
#define P_PAD 258       // >= 256 (full acc width) + even for float2 stores
#define M_PAD 97
#define MAXINV 32

// ---- smem byte offsets ----
#define SM_A0    0                 // 64*36*4 = 9216
#define SM_A1    9216
#define SM_B0    18432             // 32768
#define SM_B1    51200             // ends 83968
// epilogue aliases GEMM region:
#define SM_PHONE 0                 // 64*258*4 = 66048
#define SM_PH    66048             // 64*97*4  = 24832 -> 90880
#define SM_TBL   90880             // icnt: 96*4 -> 91264
#define SM_ILIST 91264             // 96*32 = 3072 -> 94336
#define SM_MAXV  94336             // 64*4
#define SM_LSEV  94592             // 64*4
#define SM_TOTAL 94848

__device__ float         g_Bp[NCHUNK * 8192];   // fragment-permuted B (tf32-rounded)
__device__ int           g_icnt[NM];
__device__ unsigned char g_ilist[NM * MAXINV];

// ---------------- helpers ----------------
__device__ __forceinline__ uint32_t smem_u32(const void* p) {
    uint32_t a;
    asm("{ .reg .u64 t; cvta.to.shared.u64 t, %1; cvt.u32.u64 %0, t; }" : "=r"(a) : "l"(p));
    return a;
}
__device__ __forceinline__ void cp16(uint32_t dst, const void* src) {
    asm volatile("cp.async.cg.shared.global [%0], [%1], 16;" :: "r"(dst), "l"(src));
}
#define CP_COMMIT() asm volatile("cp.async.commit_group;" ::: "memory")
#define CP_WAIT(N)  asm volatile("cp.async.wait_group %0;" :: "n"(N) : "memory")

// m16n8k8 tf32 MMA, D += A*B (C=D)
__device__ __forceinline__ void mma_tf32(float* d, const uint32_t* a, uint32_t b0, uint32_t b1) {
    asm volatile(
        "mma.sync.aligned.m16n8k8.row.col.f32.tf32.tf32.f32 "
        "{%0,%1,%2,%3}, {%4,%5,%6,%7}, {%8,%9}, {%0,%1,%2,%3};"
        : "+f"(d[0]), "+f"(d[1]), "+f"(d[2]), "+f"(d[3])
        : "r"(a[0]), "r"(a[1]), "r"(a[2]), "r"(a[3]), "r"(b0), "r"(b1));
}

// ---------------- prologue kernels ----------------
// Inverse map: phoneme -> list of phones (ballot compaction keeps order).
__global__ void build_inv_kernel(const float* __restrict__ mapping) {
    int m    = (blockIdx.x * blockDim.x + threadIdx.x) >> 5;
    int lane = threadIdx.x & 31;
    if (m >= NM) return;
    int cnt = 0;
    for (int base = 0; base < NP; base += 32) {
        int p = base + lane;
        bool hit = (p < NP) && (mapping[m * NP + p] > 0.0f);
        unsigned bal = __ballot_sync(0xffffffffu, hit);
        if (hit) {
            int pos = cnt + __popc(bal & ((1u << lane) - 1u));
            if (pos < MAXINV) g_ilist[m * MAXINV + pos] = (unsigned char)p;
        }
        cnt += __popc(bal);
    }
    if (lane == 0) g_icnt[m] = (cnt < MAXINV) ? cnt : MAXINV;
}

// Permute B into per-chunk fragment order: [chunk][ntile 32][kstep 4][lane 32][2]
// frag value for lane t, reg i:  f2p[k = kc*32 + ks*8 + (t&3) + 4*i][n = nt*8 + (t>>2)]
// Values pre-rounded to tf32 (round-to-nearest) so the MMA sees rounded, not truncated, B.
__global__ void pack_b_kernel(const float* __restrict__ f2p) {
    int idx = blockIdx.x * blockDim.x + threadIdx.x;
    if (idx >= NCHUNK * 8192) return;
    int kc   = idx >> 13;
    int rem  = idx & 8191;
    int nt   = rem >> 8;
    int r2   = rem & 255;
    int ks   = r2 >> 6;
    int lane = (r2 >> 1) & 31;
    int i    = r2 & 1;
    int n = nt * 8 + (lane >> 2);
    int k = kc * KC + ks * 8 + (lane & 3) + 4 * i;
    float v = (n < NP) ? f2p[k * NP + n] : 0.0f;
    uint32_t t;
    asm("cvt.rna.tf32.f32 %0, %1;" : "=r"(t) : "f"(v));
    g_Bp[idx] = __uint_as_float(t);
}

// ---------------- main kernel ----------------
__global__ __launch_bounds__(256, 1)
void phon_mma_kernel(const float* __restrict__ enc, float* __restrict__ out) {
    extern __shared__ char smem[];
    const uint32_t sbase = smem_u32(smem);
    const int tid  = threadIdx.x;
    const int wid  = tid >> 5;
    const int lane = tid & 31;
    const int wm   = wid >> 2;   // 0..1
    const int wn   = wid & 3;    // 0..3
    const int row0 = blockIdx.x * TM;

    int*           sicnt  = (int*)(smem + SM_TBL);
    unsigned char* silist = (unsigned char*)(smem + SM_ILIST);
    float*         sMaxv  = (float*)(smem + SM_MAXV);
    float*         sLsev  = (float*)(smem + SM_LSEV);

    // stage inverse-map tables (covered by first __syncthreads)
    if (tid < NM) sicnt[tid] = g_icnt[tid];
    for (int i = tid; i < NM * MAXINV; i += 256) silist[i] = g_ilist[i];

    float acc[2][8][4];
    #pragma unroll
    for (int i = 0; i < 2; i++)
        #pragma unroll
        for (int j = 0; j < 8; j++)
            #pragma unroll
            for (int c = 0; c < 4; c++) acc[i][j][c] = 0.0f;

    auto issue_chunk = [&](int kc, int buf) {
        uint32_t adst = sbase + (buf ? SM_A1 : SM_A0);
        #pragma unroll
        for (int it = 0; it < 2; it++) {
            int i4 = tid + it * 256;
            int r = i4 >> 3, g = i4 & 7;
            cp16(adst + (uint32_t)(r * A_PAD + g * 4) * 4,
                 enc + (size_t)(row0 + r) * HD + kc * KC + g * 4);
        }
        uint32_t bdst = sbase + (buf ? SM_B1 : SM_B0);
        const float* bsrc = g_Bp + (size_t)kc * 8192;
        #pragma unroll
        for (int it = 0; it < 8; it++) {
            int i4 = tid + it * 256;
            cp16(bdst + (uint32_t)i4 * 16, bsrc + (size_t)i4 * 4);
        }
    };

    auto do_chunk = [&](int buf) {
        const float* sA = (const float*)(smem + (buf ? SM_A1 : SM_A0));
        const char*  sB = smem + (buf ? SM_B1 : SM_B0);
        #pragma unroll
        for (int ks = 0; ks < 4; ks++) {
            uint32_t afr[2][4];
            #pragma unroll
            for (int i = 0; i < 2; i++) {
                const float* ap = sA + (wm * 32 + i * 16 + (lane >> 2)) * A_PAD
                                     + ks * 8 + (lane & 3);
                afr[i][0] = __float_as_uint(ap[0]);
                afr[i][1] = __float_as_uint(ap[8 * A_PAD]);
                afr[i][2] = __float_as_uint(ap[4]);
                afr[i][3] = __float_as_uint(ap[8 * A_PAD + 4]);
            }
            float2 bfr[8];
            #pragma unroll
            for (int j = 0; j < 8; j++) {
                int nt = wn * 8 + j;
                bfr[j] = *(const float2*)(sB + ((nt * 4 + ks) * 32 + lane) * 8);
            }
            #pragma unroll
            for (int i = 0; i < 2; i++)
                #pragma unroll
                for (int j = 0; j < 8; j++)
                    mma_tf32(acc[i][j], afr[i],
                             __float_as_uint(bfr[j].x), __float_as_uint(bfr[j].y));
        }
    };

    issue_chunk(0, 0);
    CP_COMMIT();
    for (int kc = 0; kc < NCHUNK; kc++) {
        if (kc + 1 < NCHUNK) {
            issue_chunk(kc + 1, (kc + 1) & 1);
            CP_COMMIT();
            CP_WAIT(1);
        } else {
            CP_WAIT(0);
        }
        __syncthreads();
        do_chunk(kc & 1);
        __syncthreads();
    }

    // ---- epilogue ----
    const float scale = 0.039528470752104741f;  // 1/sqrt(640)
    float*         sPhone = (float*)(smem + SM_PHONE);
    float*         sPh    = (float*)(smem + SM_PH);

    // acc -> phone logits in smem (aliases GEMM buffers; loop ended with barrier).
    // P_PAD=258 >= 256 so cols 230..255 are in-row padding, never cross rows.
    #pragma unroll
    for (int i = 0; i < 2; i++) {
        int r = wm * 32 + i * 16 + (lane >> 2);
        #pragma unroll
        for (int j = 0; j < 8; j++) {
            int c = wn * 64 + j * 8 + (lane & 3) * 2;
            float2 v0 = make_float2(acc[i][j][0] * scale, acc[i][j][1] * scale);
            float2 v1 = make_float2(acc[i][j][2] * scale, acc[i][j][3] * scale);
            *(float2*)(sPhone + r * P_PAD + c)       = v0;
            *(float2*)(sPhone + (r + 8) * P_PAD + c) = v1;
        }
    }
    __syncthreads();

    // gather-max via inverse map: 64 rows x 96 phonemes over 256 threads
    for (int idx = tid; idx < TM * NM; idx += 256) {
        int r = idx / NM;
        int m = idx - r * NM;
        int cnt = sicnt[m];
        const unsigned char* lst = silist + m * MAXINV;
        float mx = -INFINITY;
        for (int c = 0; c < cnt; c++)
            mx = fmaxf(mx, sPhone[r * P_PAD + lst[c]]);
        sPh[r * M_PAD + m] = mx;
    }
    __syncthreads();

    // per-row max + logsumexp
    if (tid < TM) {
        const float* row = sPh + tid * M_PAD;
        float mx = -INFINITY;
        for (int m = 0; m < NM; m++) mx = fmaxf(mx, row[m]);
        float s = 0.0f;
        for (int m = 0; m < NM; m++) s += expf(row[m] - mx);
        sMaxv[tid] = mx;
        sLsev[tid] = logf(s);
    }
    __syncthreads();

    // coalesced output
    for (int idx = tid; idx < TM * NM; idx += 256) {
        int r = idx / NM;
        int m = idx - r * NM;
        out[(size_t)(row0 + r) * NM + m] = sPh[r * M_PAD + m] - sMaxv[r] - sLsev[r];
    }
}

extern "C" void kernel_launch(void* const* d_in, const int* in_sizes, int n_in,
                              void* d_out, int out_size) {
    const float* enc     = (const float*)d_in[0];
    const float* f2p     = (const float*)d_in[1];
    const float* mapping = (const float*)d_in[2];
    float*       out     = (float*)d_out;

    cudaFuncSetAttribute(phon_mma_kernel,
                         cudaFuncAttributeMaxDynamicSharedMemorySize, SM_TOTAL);

    build_inv_kernel<<<(NM * 32 + 255) / 256, 256>>>(mapping);
    pack_b_kernel<<<(NCHUNK * 8192 + 255) / 256, 256>>>(f2p);
    phon_mma_kernel<<<NROWS / TM, 256, SM_TOTAL>>>(enc, out);
}